// round 5
// baseline (speedup 1.0000x reference)
#include <cuda_runtime.h>
#include <cub/cub.cuh>
#include <cstdint>
#include <math.h>

// Problem shape (fixed): B=4, H=8, S=1024, D=64
#define SLEN 1024
#define HD   64
#define NBH  32
#define NROWS (NBH * SLEN)           // 32768
#define NTOT  ((size_t)NROWS * SLEN) // 33554432 = 2^25
#define BIN_SHIFT 12
#define NBINS (1u << 18)             // 262144 bins, 1 MiB

typedef unsigned long long ull;

// ---------------- scratch ---------------------------------------------------
__device__ float g_score[NROWS * SLEN];          // 128 MiB raw scores
__device__ unsigned int g_hist[NBINS];           // 1 MiB counts
__device__ unsigned int g_scan[NBINS];           // 1 MiB exclusive prefix
__device__ float g_ttab[NBINS];                  // 1 MiB  t = -log(rank prob)
__device__ float g_invq[NROWS];
__device__ float g_invk[NROWS];
__device__ unsigned char g_temp[8u * 1024u * 1024u];  // CUB scan temp

// ---------------- f32x2 helpers (sm_103a) -----------------------------------
__device__ __forceinline__ ull pack2(float a, float b) {
    ull r; asm("mov.b64 %0, {%1,%2};" : "=l"(r) : "f"(a), "f"(b)); return r;
}
__device__ __forceinline__ ull fma2(ull a, ull b, ull c) {
    ull d; asm("fma.rn.f32x2 %0, %1, %2, %3;" : "=l"(d) : "l"(a), "l"(b), "l"(c));
    return d;
}
__device__ __forceinline__ float2 unpack2(ull v) {
    float2 f; asm("mov.b64 {%0,%1}, %2;" : "=f"(f.x), "=f"(f.y) : "l"(v));
    return f;
}
__device__ __forceinline__ unsigned bin_of(float v) {
    unsigned b = __float_as_uint(fabsf(v)) >> BIN_SHIFT;   // monotone in |v|
    return min(b, NBINS - 1u);
}
__device__ __forceinline__ unsigned sw(unsigned a) {      // 128B-line swizzle
    return a ^ ((a >> 3) & 0x70u);
}

// ---------------- kernel 0: zero histogram ----------------------------------
__global__ __launch_bounds__(256) void zero_hist_kernel() {
    unsigned i = blockIdx.x * 256 + threadIdx.x;
    ((uint4*)g_hist)[i] = make_uint4(0u, 0u, 0u, 0u);
}

// ---------------- kernel 1: inverse row norms -------------------------------
__global__ __launch_bounds__(256) void norms_kernel(const float* __restrict__ Q,
                                                    const float* __restrict__ K) {
    int w = (blockIdx.x * 256 + threadIdx.x) >> 5;
    int lane = threadIdx.x & 31;
    const float* src; float* dst; int row;
    if (w < NROWS) { src = Q; dst = g_invq; row = w; }
    else           { src = K; dst = g_invk; row = w - NROWS; }
    const float* p = src + (size_t)row * HD;
    float a = p[lane], b = p[lane + 32];
    float s = a * a + b * b;
    #pragma unroll
    for (int o = 16; o; o >>= 1) s += __shfl_xor_sync(0xffffffffu, s, o);
    if (lane == 0) dst[row] = 1.0f / (sqrtf(s) + 1e-5f);
}

// ---------------- kernel 2: score GEMM (128x128 tile, 8x8/thread) + hist ----
__global__ __launch_bounds__(256) void score_kernel(const float* __restrict__ Q,
                                                    const float* __restrict__ K) {
    __shared__ float Qs[128 * 33];   // i-major, odd stride -> conflict-free A
    __shared__ float Ks[32 * 128];   // k-major, SW128-swizzled -> conflict-free B
    int bh = blockIdx.z;
    int i0 = blockIdx.y * 128, j0 = blockIdx.x * 128;
    const float* Qb = Q + (size_t)bh * SLEN * HD;
    const float* Kb = K + (size_t)bh * SLEN * HD;
    int tid = threadIdx.x;
    int tx = tid & 15, ty = tid >> 4;

    ull acc[8][4];
    #pragma unroll
    for (int ii = 0; ii < 8; ii++)
        #pragma unroll
        for (int p = 0; p < 4; p++) acc[ii][p] = 0ull;

    #pragma unroll
    for (int c = 0; c < 2; c++) {          // k chunks of 32
        int k0 = c * 32;
        if (c) __syncthreads();
        #pragma unroll
        for (int pass = 0; pass < 4; pass++) {
            int row = (tid >> 3) + pass * 32;
            int kq = (tid & 7) * 4;
            float4 q4 = *(const float4*)&Qb[(i0 + row) * HD + k0 + kq];
            float* qd = &Qs[row * 33 + kq];
            qd[0] = q4.x; qd[1] = q4.y; qd[2] = q4.z; qd[3] = q4.w;
            float4 k4 = *(const float4*)&Kb[(j0 + row) * HD + k0 + kq];
            #pragma unroll
            for (int e = 0; e < 4; e++) {
                unsigned a = (unsigned)(kq + e) * 512u + (unsigned)row * 4u;
                Ks[sw(a) >> 2] = (&k4.x)[e];
            }
        }
        __syncthreads();
        #pragma unroll
        for (int k = 0; k < 32; k++) {
            unsigned a0 = (unsigned)k * 512u + (unsigned)tx * 32u;
            float4 b0 = *(const float4*)&Ks[sw(a0) >> 2];
            float4 b1 = *(const float4*)&Ks[sw(a0 + 16u) >> 2];
            ull bv0 = pack2(b0.x, b0.y), bv1 = pack2(b0.z, b0.w);
            ull bv2 = pack2(b1.x, b1.y), bv3 = pack2(b1.z, b1.w);
            #pragma unroll
            for (int ii = 0; ii < 8; ii++) {
                float av = Qs[(ty * 8 + ii) * 33 + k];
                ull a2 = pack2(av, av);
                acc[ii][0] = fma2(a2, bv0, acc[ii][0]);
                acc[ii][1] = fma2(a2, bv1, acc[ii][1]);
                acc[ii][2] = fma2(a2, bv2, acc[ii][2]);
                acc[ii][3] = fma2(a2, bv3, acc[ii][3]);
            }
        }
    }

    // epilogue: normalize, write raw scores, build histogram (RED, no return)
    int jb = j0 + tx * 8;
    float ikv[8];
    #pragma unroll
    for (int jj = 0; jj < 8; jj++) ikv[jj] = g_invk[bh * SLEN + jb + jj];
    #pragma unroll
    for (int ii = 0; ii < 8; ii++) {
        int row = bh * SLEN + i0 + ty * 8 + ii;
        float iq = g_invq[row];
        float2 c0 = unpack2(acc[ii][0]);
        float2 c1 = unpack2(acc[ii][1]);
        float2 c2 = unpack2(acc[ii][2]);
        float2 c3 = unpack2(acc[ii][3]);
        float v[8];
        v[0] = c0.x * iq * ikv[0]; v[1] = c0.y * iq * ikv[1];
        v[2] = c1.x * iq * ikv[2]; v[3] = c1.y * iq * ikv[3];
        v[4] = c2.x * iq * ikv[4]; v[5] = c2.y * iq * ikv[5];
        v[6] = c3.x * iq * ikv[6]; v[7] = c3.y * iq * ikv[7];
        size_t idx = (size_t)row * SLEN + jb;
        *(float4*)&g_score[idx]     = make_float4(v[0], v[1], v[2], v[3]);
        *(float4*)&g_score[idx + 4] = make_float4(v[4], v[5], v[6], v[7]);
        #pragma unroll
        for (int e = 0; e < 8; e++) atomicAdd(&g_hist[bin_of(v[e])], 1u);
    }
}

// ---------------- kernel 2.5: per-bin t table --------------------------------
// midpoint rank for the whole bin: rank = prefix + (cnt-1)/2
__global__ __launch_bounds__(256) void ttab_kernel() {
    unsigned i = blockIdx.x * 256 + threadIdx.x;
    unsigned cnt = g_hist[i];
    unsigned pre = g_scan[i];
    float p = (float)pre + 0.5f * (float)(cnt > 0 ? cnt - 1 : 0);
    float r = p * (1.0f / 33554431.0f) + (1.0f / 33554432.0f);
    g_ttab[i] = -__logf(r);
}

// ---------------- kernel 3: fused transform + rowsum + out GEMM --------------
// 128 blocks, 256 rows each. Staging thread t owns row i0+t: reads raw P,
// gathers per-bin t from g_ttab (L1-resident hot set), applies sign, stores
// into smem, accumulates the row L1 sum in a register across all 32 chunks.
__global__ __launch_bounds__(256) void out_kernel(const float* __restrict__ V,
                                                  float* __restrict__ O) {
    __shared__ float Ts[256 * 33];   // t values, i-major odd stride
    __shared__ float Vs[32 * 64];    // k-major SW128-swizzled
    __shared__ float sinv[256];
    int blk = blockIdx.x;            // 0..127
    int bh = blk >> 2;
    int i0 = blk * 256;
    const float* Vb = V + (size_t)bh * SLEN * HD;
    int tid = threadIdx.x;
    int tx = tid & 7, ty = tid >> 3;

    ull acc[8][4];
    #pragma unroll
    for (int ii = 0; ii < 8; ii++)
        #pragma unroll
        for (int p = 0; p < 4; p++) acc[ii][p] = 0ull;
    float srow = 0.0f;

    for (int c = 0; c < 32; c++) {   // k chunks of 32
        if (c) __syncthreads();
        // stage V chunk (swizzled)
        {
            int kv = tid >> 3;
            int d8 = (tid & 7) * 8;
            const float* vp = &Vb[(c * 32 + kv) * HD + d8];
            #pragma unroll
            for (int h = 0; h < 2; h++) {
                float4 v4 = *(const float4*)&vp[h * 4];
                unsigned a = (unsigned)kv * 256u + (unsigned)(d8 + h * 4) * 4u;
                *(float4*)&Vs[sw(a) >> 2] = v4;
            }
        }
        // stage + transform P: thread owns row i0+tid; table gather, no atomics
        {
            const float* pr = g_score + (size_t)(i0 + tid) * SLEN + c * 32;
            float* trow = &Ts[tid * 33];
            #pragma unroll
            for (int q = 0; q < 8; q++) {
                float4 v4 = *(const float4*)&pr[q * 4];
                #pragma unroll
                for (int e = 0; e < 4; e++) {
                    float v = (&v4.x)[e];
                    float t = __ldg(&g_ttab[bin_of(v)]);
                    t = (v > 0.0f) ? t : ((v < 0.0f) ? -t : 0.0f);
                    srow += fabsf(t);
                    trow[q * 4 + e] = t;
                }
            }
        }
        __syncthreads();
        #pragma unroll
        for (int k = 0; k < 32; k++) {
            unsigned a0 = (unsigned)k * 256u + (unsigned)tx * 32u;
            float4 b0 = *(const float4*)&Vs[sw(a0) >> 2];
            float4 b1 = *(const float4*)&Vs[sw(a0 + 16u) >> 2];
            ull bv0 = pack2(b0.x, b0.y), bv1 = pack2(b0.z, b0.w);
            ull bv2 = pack2(b1.x, b1.y), bv3 = pack2(b1.z, b1.w);
            #pragma unroll
            for (int ii = 0; ii < 8; ii++) {
                float av = Ts[(ty * 8 + ii) * 33 + k];
                ull a2 = pack2(av, av);
                acc[ii][0] = fma2(a2, bv0, acc[ii][0]);
                acc[ii][1] = fma2(a2, bv1, acc[ii][1]);
                acc[ii][2] = fma2(a2, bv2, acc[ii][2]);
                acc[ii][3] = fma2(a2, bv3, acc[ii][3]);
            }
        }
    }

    sinv[tid] = 1.0f / srow;
    __syncthreads();

    int d0 = tx * 8;
    #pragma unroll
    for (int ii = 0; ii < 8; ii++) {
        int lrow = ty * 8 + ii;
        float s = sinv[lrow];
        float2 c0 = unpack2(acc[ii][0]);
        float2 c1 = unpack2(acc[ii][1]);
        float2 c2 = unpack2(acc[ii][2]);
        float2 c3 = unpack2(acc[ii][3]);
        size_t oidx = (size_t)(i0 + lrow) * HD + d0;
        *(float4*)&O[oidx]     = make_float4(c0.x * s, c0.y * s, c1.x * s, c1.y * s);
        *(float4*)&O[oidx + 4] = make_float4(c2.x * s, c2.y * s, c3.x * s, c3.y * s);
    }
}

// ---------------- launcher ---------------------------------------------------
extern "C" void kernel_launch(void* const* d_in, const int* in_sizes, int n_in,
                              void* d_out, int out_size) {
    const float* Q = (const float*)d_in[0];
    const float* K = (const float*)d_in[1];
    const float* V = (const float*)d_in[2];
    float* O = (float*)d_out;

    zero_hist_kernel<<<NBINS / 4 / 256, 256>>>();
    norms_kernel<<<8192, 256>>>(Q, K);
    score_kernel<<<dim3(8, 8, NBH), 256>>>(Q, K);

    void* tmp; void* hist; void* scan;
    cudaGetSymbolAddress(&tmp, g_temp);
    cudaGetSymbolAddress(&hist, g_hist);
    cudaGetSymbolAddress(&scan, g_scan);
    size_t temp_bytes = sizeof(g_temp);
    cub::DeviceScan::ExclusiveSum(tmp, temp_bytes,
                                  (unsigned int*)hist, (unsigned int*)scan,
                                  (int)NBINS);
    ttab_kernel<<<NBINS / 256, 256>>>();

    out_kernel<<<128, 256>>>(V, O);
}

// round 6
// speedup vs baseline: 1.4771x; 1.4771x over previous
#include <cuda_runtime.h>
#include <cub/cub.cuh>
#include <cstdint>
#include <math.h>

// Problem shape (fixed): B=4, H=8, S=1024, D=64
#define SLEN 1024
#define HD   64
#define NBH  32
#define NROWS (NBH * SLEN)           // 32768
#define NTOT  ((size_t)NROWS * SLEN) // 33554432 = 2^25
#define BIN_SHIFT 9
#define NBINS (1u << 22)             // 4.19M bins

typedef unsigned long long ull;

// ---------------- scratch ---------------------------------------------------
__device__ float g_score[NROWS * SLEN];          // 128 MiB raw scores
__device__ unsigned int g_hist[NBINS];           // 16 MiB counts
__device__ unsigned int g_scan[NBINS];           // 16 MiB exclusive prefix
__device__ float g_ttab[NBINS];                  // 16 MiB  t = -log(rank prob)
__device__ float g_invq[NROWS];
__device__ float g_invk[NROWS];
__device__ unsigned char g_temp[16u * 1024u * 1024u];  // CUB scan temp

// ---------------- f32x2 helpers (sm_103a) -----------------------------------
__device__ __forceinline__ ull pack2(float a, float b) {
    ull r; asm("mov.b64 %0, {%1,%2};" : "=l"(r) : "f"(a), "f"(b)); return r;
}
__device__ __forceinline__ ull fma2(ull a, ull b, ull c) {
    ull d; asm("fma.rn.f32x2 %0, %1, %2, %3;" : "=l"(d) : "l"(a), "l"(b), "l"(c));
    return d;
}
__device__ __forceinline__ float2 unpack2(ull v) {
    float2 f; asm("mov.b64 {%0,%1}, %2;" : "=f"(f.x), "=f"(f.y) : "l"(v));
    return f;
}
__device__ __forceinline__ unsigned bin_of(float v) {
    unsigned b = __float_as_uint(fabsf(v)) >> BIN_SHIFT;   // monotone in |v|
    return min(b, NBINS - 1u);
}
__device__ __forceinline__ unsigned sw(unsigned a) {      // 128B-line swizzle
    return a ^ ((a >> 3) & 0x70u);
}

// ---------------- kernel 0: zero histogram ----------------------------------
__global__ __launch_bounds__(256) void zero_hist_kernel() {
    unsigned i = blockIdx.x * 256 + threadIdx.x;
    ((uint4*)g_hist)[i] = make_uint4(0u, 0u, 0u, 0u);
}

// ---------------- kernel 1: inverse row norms -------------------------------
__global__ __launch_bounds__(256) void norms_kernel(const float* __restrict__ Q,
                                                    const float* __restrict__ K) {
    int w = (blockIdx.x * 256 + threadIdx.x) >> 5;
    int lane = threadIdx.x & 31;
    const float* src; float* dst; int row;
    if (w < NROWS) { src = Q; dst = g_invq; row = w; }
    else           { src = K; dst = g_invk; row = w - NROWS; }
    const float* p = src + (size_t)row * HD;
    float a = p[lane], b = p[lane + 32];
    float s = a * a + b * b;
    #pragma unroll
    for (int o = 16; o; o >>= 1) s += __shfl_xor_sync(0xffffffffu, s, o);
    if (lane == 0) dst[row] = 1.0f / (sqrtf(s) + 1e-5f);
}

// ---------------- kernel 2: score GEMM (128x128 tile, 8x8/thread) + hist ----
__global__ __launch_bounds__(256) void score_kernel(const float* __restrict__ Q,
                                                    const float* __restrict__ K) {
    __shared__ float Qs[128 * 33];   // i-major, odd stride -> conflict-free A
    __shared__ float Ks[32 * 128];   // k-major, SW128-swizzled -> conflict-free B
    int bh = blockIdx.z;
    int i0 = blockIdx.y * 128, j0 = blockIdx.x * 128;
    const float* Qb = Q + (size_t)bh * SLEN * HD;
    const float* Kb = K + (size_t)bh * SLEN * HD;
    int tid = threadIdx.x;
    int tx = tid & 15, ty = tid >> 4;

    ull acc[8][4];
    #pragma unroll
    for (int ii = 0; ii < 8; ii++)
        #pragma unroll
        for (int p = 0; p < 4; p++) acc[ii][p] = 0ull;

    #pragma unroll
    for (int c = 0; c < 2; c++) {          // k chunks of 32
        int k0 = c * 32;
        if (c) __syncthreads();
        #pragma unroll
        for (int pass = 0; pass < 4; pass++) {
            int row = (tid >> 3) + pass * 32;
            int kq = (tid & 7) * 4;
            float4 q4 = *(const float4*)&Qb[(i0 + row) * HD + k0 + kq];
            float* qd = &Qs[row * 33 + kq];
            qd[0] = q4.x; qd[1] = q4.y; qd[2] = q4.z; qd[3] = q4.w;
            float4 k4 = *(const float4*)&Kb[(j0 + row) * HD + k0 + kq];
            #pragma unroll
            for (int e = 0; e < 4; e++) {
                unsigned a = (unsigned)(kq + e) * 512u + (unsigned)row * 4u;
                Ks[sw(a) >> 2] = (&k4.x)[e];
            }
        }
        __syncthreads();
        #pragma unroll
        for (int k = 0; k < 32; k++) {
            unsigned a0 = (unsigned)k * 512u + (unsigned)tx * 32u;
            float4 b0 = *(const float4*)&Ks[sw(a0) >> 2];
            float4 b1 = *(const float4*)&Ks[sw(a0 + 16u) >> 2];
            ull bv0 = pack2(b0.x, b0.y), bv1 = pack2(b0.z, b0.w);
            ull bv2 = pack2(b1.x, b1.y), bv3 = pack2(b1.z, b1.w);
            #pragma unroll
            for (int ii = 0; ii < 8; ii++) {
                float av = Qs[(ty * 8 + ii) * 33 + k];
                ull a2 = pack2(av, av);
                acc[ii][0] = fma2(a2, bv0, acc[ii][0]);
                acc[ii][1] = fma2(a2, bv1, acc[ii][1]);
                acc[ii][2] = fma2(a2, bv2, acc[ii][2]);
                acc[ii][3] = fma2(a2, bv3, acc[ii][3]);
            }
        }
    }

    // epilogue: normalize, write raw scores, build histogram (RED, no return)
    int jb = j0 + tx * 8;
    float ikv[8];
    #pragma unroll
    for (int jj = 0; jj < 8; jj++) ikv[jj] = g_invk[bh * SLEN + jb + jj];
    #pragma unroll
    for (int ii = 0; ii < 8; ii++) {
        int row = bh * SLEN + i0 + ty * 8 + ii;
        float iq = g_invq[row];
        float2 c0 = unpack2(acc[ii][0]);
        float2 c1 = unpack2(acc[ii][1]);
        float2 c2 = unpack2(acc[ii][2]);
        float2 c3 = unpack2(acc[ii][3]);
        float v[8];
        v[0] = c0.x * iq * ikv[0]; v[1] = c0.y * iq * ikv[1];
        v[2] = c1.x * iq * ikv[2]; v[3] = c1.y * iq * ikv[3];
        v[4] = c2.x * iq * ikv[4]; v[5] = c2.y * iq * ikv[5];
        v[6] = c3.x * iq * ikv[6]; v[7] = c3.y * iq * ikv[7];
        size_t idx = (size_t)row * SLEN + jb;
        *(float4*)&g_score[idx]     = make_float4(v[0], v[1], v[2], v[3]);
        *(float4*)&g_score[idx + 4] = make_float4(v[4], v[5], v[6], v[7]);
        #pragma unroll
        for (int e = 0; e < 8; e++) atomicAdd(&g_hist[bin_of(v[e])], 1u);
    }
}

// ---------------- kernel 2.5: per-bin t table --------------------------------
// midpoint rank for the whole bin: rank = prefix + (cnt-1)/2
__global__ __launch_bounds__(256) void ttab_kernel() {
    unsigned i = blockIdx.x * 256 + threadIdx.x;
    unsigned cnt = g_hist[i];
    unsigned pre = g_scan[i];
    float p = (float)pre + 0.5f * (float)(cnt > 0 ? cnt - 1 : 0);
    float r = p * (1.0f / 33554431.0f) + (1.0f / 33554432.0f);
    g_ttab[i] = -__logf(r);
}

// ---------------- kernel 3: fused transform + rowsum + out GEMM --------------
// 256 blocks x 128 rows (2 blocks/SM co-resident -> staging overlaps math).
// Two staging threads per row (16 cols each): load raw P, gather per-bin t,
// apply sign, store to smem, accumulate partial row L1 sums.
__global__ __launch_bounds__(256) void out_kernel(const float* __restrict__ V,
                                                  float* __restrict__ O) {
    __shared__ float Ts[128 * 33];   // t values, i-major odd stride
    __shared__ float Vs[32 * 64];    // k-major SW128-swizzled
    __shared__ float spart[256];
    __shared__ float sinv[128];
    int blk = blockIdx.x;            // 0..255
    int bh = blk >> 3;
    int i0 = blk * 128;
    const float* Vb = V + (size_t)bh * SLEN * HD;
    int tid = threadIdx.x;
    int tx = tid & 7, ty = tid >> 3;     // math: tx d-group(8 cols), ty row-group(4 rows)
    int prow = tid & 127, phalf = tid >> 7;  // staging: 2 threads per row

    ull acc[4][4];
    #pragma unroll
    for (int ii = 0; ii < 4; ii++)
        #pragma unroll
        for (int p = 0; p < 4; p++) acc[ii][p] = 0ull;
    float srow = 0.0f;

    for (int c = 0; c < 32; c++) {   // k chunks of 32
        if (c) __syncthreads();
        // stage V chunk (swizzled): 32 rows x 64 cols
        {
            int kv = tid >> 3;
            int d8 = (tid & 7) * 8;
            const float* vp = &Vb[(c * 32 + kv) * HD + d8];
            #pragma unroll
            for (int h = 0; h < 2; h++) {
                float4 v4 = *(const float4*)&vp[h * 4];
                unsigned a = (unsigned)kv * 256u + (unsigned)(d8 + h * 4) * 4u;
                *(float4*)&Vs[sw(a) >> 2] = v4;
            }
        }
        // stage + transform P: 16 cols of row i0+prow; batched for MLP
        {
            const float* pr = g_score + (size_t)(i0 + prow) * SLEN + c * 32 + phalf * 16;
            float v[16];
            #pragma unroll
            for (int q = 0; q < 4; q++)
                *(float4*)&v[q * 4] = *(const float4*)&pr[q * 4];
            float t[16];
            #pragma unroll
            for (int e = 0; e < 16; e++)
                t[e] = __ldg(&g_ttab[bin_of(v[e])]);
            float* trow = &Ts[prow * 33 + phalf * 16];
            #pragma unroll
            for (int e = 0; e < 16; e++) {
                float tt = (v[e] > 0.0f) ? t[e] : ((v[e] < 0.0f) ? -t[e] : 0.0f);
                srow += fabsf(tt);
                trow[e] = tt;
            }
        }
        __syncthreads();
        #pragma unroll
        for (int k = 0; k < 32; k++) {
            unsigned a0 = (unsigned)k * 256u + (unsigned)tx * 32u;
            float4 b0 = *(const float4*)&Vs[sw(a0) >> 2];
            float4 b1 = *(const float4*)&Vs[sw(a0 + 16u) >> 2];
            ull bv0 = pack2(b0.x, b0.y), bv1 = pack2(b0.z, b0.w);
            ull bv2 = pack2(b1.x, b1.y), bv3 = pack2(b1.z, b1.w);
            #pragma unroll
            for (int ii = 0; ii < 4; ii++) {
                float av = Ts[(ty * 4 + ii) * 33 + k];   // banks (r+k)%32: 4 distinct
                ull a2 = pack2(av, av);
                acc[ii][0] = fma2(a2, bv0, acc[ii][0]);
                acc[ii][1] = fma2(a2, bv1, acc[ii][1]);
                acc[ii][2] = fma2(a2, bv2, acc[ii][2]);
                acc[ii][3] = fma2(a2, bv3, acc[ii][3]);
            }
        }
    }

    spart[tid] = srow;
    __syncthreads();
    if (tid < 128) sinv[tid] = 1.0f / (spart[tid] + spart[tid + 128]);
    __syncthreads();

    int d0 = tx * 8;
    #pragma unroll
    for (int ii = 0; ii < 4; ii++) {
        int lrow = ty * 4 + ii;
        float s = sinv[lrow];
        float2 c0 = unpack2(acc[ii][0]);
        float2 c1 = unpack2(acc[ii][1]);
        float2 c2 = unpack2(acc[ii][2]);
        float2 c3 = unpack2(acc[ii][3]);
        size_t oidx = (size_t)(i0 + lrow) * HD + d0;
        *(float4*)&O[oidx]     = make_float4(c0.x * s, c0.y * s, c1.x * s, c1.y * s);
        *(float4*)&O[oidx + 4] = make_float4(c2.x * s, c2.y * s, c3.x * s, c3.y * s);
    }
}

// ---------------- launcher ---------------------------------------------------
extern "C" void kernel_launch(void* const* d_in, const int* in_sizes, int n_in,
                              void* d_out, int out_size) {
    const float* Q = (const float*)d_in[0];
    const float* K = (const float*)d_in[1];
    const float* V = (const float*)d_in[2];
    float* O = (float*)d_out;

    zero_hist_kernel<<<NBINS / 4 / 256, 256>>>();
    norms_kernel<<<8192, 256>>>(Q, K);
    score_kernel<<<dim3(8, 8, NBH), 256>>>(Q, K);

    void* tmp; void* hist; void* scan;
    cudaGetSymbolAddress(&tmp, g_temp);
    cudaGetSymbolAddress(&hist, g_hist);
    cudaGetSymbolAddress(&scan, g_scan);
    size_t temp_bytes = sizeof(g_temp);
    cub::DeviceScan::ExclusiveSum(tmp, temp_bytes,
                                  (unsigned int*)hist, (unsigned int*)scan,
                                  (int)NBINS);
    ttab_kernel<<<NBINS / 256, 256>>>();

    out_kernel<<<256, 256>>>(V, O);
}

// round 7
// speedup vs baseline: 2.6163x; 1.7713x over previous
#include <cuda_runtime.h>
#include <cstdint>
#include <math.h>

// Problem shape (fixed): B=4, H=8, S=1024, D=64
#define SLEN 1024
#define HD   64
#define NBH  32
#define NROWS (NBH * SLEN)           // 32768
#define NTOT  ((size_t)NROWS * SLEN) // 33554432 = 2^25
#define NBINS 4096                   // bits >> 18 : 8 exp + 5 mantissa bits

typedef unsigned long long ull;

// ---------------- scratch ---------------------------------------------------
__device__ float g_score[NROWS * SLEN];          // 128 MiB raw scores
__device__ unsigned int g_hist[NBINS];           // 16 KiB counts
__device__ float g_ttab[NBINS + 1];              // edge t values
__device__ float g_invq[NROWS];
__device__ float g_invk[NROWS];

// ---------------- f32x2 helpers (sm_103a) -----------------------------------
__device__ __forceinline__ ull pack2(float a, float b) {
    ull r; asm("mov.b64 %0, {%1,%2};" : "=l"(r) : "f"(a), "f"(b)); return r;
}
__device__ __forceinline__ ull fma2(ull a, ull b, ull c) {
    ull d; asm("fma.rn.f32x2 %0, %1, %2, %3;" : "=l"(d) : "l"(a), "l"(b), "l"(c));
    return d;
}
__device__ __forceinline__ float2 unpack2(ull v) {
    float2 f; asm("mov.b64 {%0,%1}, %2;" : "=f"(f.x), "=f"(f.y) : "l"(v));
    return f;
}
__device__ __forceinline__ unsigned sw(unsigned a) {      // 128B-line swizzle
    return a ^ ((a >> 3) & 0x70u);
}

// ---------------- kernel 0: zero small histogram -----------------------------
__global__ void zero_hist_kernel() {
    g_hist[blockIdx.x * 256 + threadIdx.x] = 0u;
}

// ---------------- kernel 1: inverse row norms -------------------------------
__global__ __launch_bounds__(256) void norms_kernel(const float* __restrict__ Q,
                                                    const float* __restrict__ K) {
    int w = (blockIdx.x * 256 + threadIdx.x) >> 5;
    int lane = threadIdx.x & 31;
    const float* src; float* dst; int row;
    if (w < NROWS) { src = Q; dst = g_invq; row = w; }
    else           { src = K; dst = g_invk; row = w - NROWS; }
    const float* p = src + (size_t)row * HD;
    float a = p[lane], b = p[lane + 32];
    float s = a * a + b * b;
    #pragma unroll
    for (int o = 16; o; o >>= 1) s += __shfl_xor_sync(0xffffffffu, s, o);
    if (lane == 0) dst[row] = 1.0f / (sqrtf(s) + 1e-5f);
}

// ---------------- kernel 2: score GEMM + smem-private histogram -------------
__global__ __launch_bounds__(256) void score_kernel(const float* __restrict__ Q,
                                                    const float* __restrict__ K) {
    __shared__ float Qs[128 * 33];   // i-major, odd stride -> conflict-free A
    __shared__ float Ks[32 * 128];   // k-major SW128; ALIASED as hist in epilogue
    int bh = blockIdx.z;
    int i0 = blockIdx.y * 128, j0 = blockIdx.x * 128;
    const float* Qb = Q + (size_t)bh * SLEN * HD;
    const float* Kb = K + (size_t)bh * SLEN * HD;
    int tid = threadIdx.x;
    int tx = tid & 15, ty = tid >> 4;

    ull acc[8][4];
    #pragma unroll
    for (int ii = 0; ii < 8; ii++)
        #pragma unroll
        for (int p = 0; p < 4; p++) acc[ii][p] = 0ull;

    #pragma unroll
    for (int c = 0; c < 2; c++) {          // k chunks of 32
        int k0 = c * 32;
        if (c) __syncthreads();
        #pragma unroll
        for (int pass = 0; pass < 4; pass++) {
            int row = (tid >> 3) + pass * 32;
            int kq = (tid & 7) * 4;
            float4 q4 = *(const float4*)&Qb[(i0 + row) * HD + k0 + kq];
            float* qd = &Qs[row * 33 + kq];
            qd[0] = q4.x; qd[1] = q4.y; qd[2] = q4.z; qd[3] = q4.w;
            float4 k4 = *(const float4*)&Kb[(j0 + row) * HD + k0 + kq];
            #pragma unroll
            for (int e = 0; e < 4; e++) {
                unsigned a = (unsigned)(kq + e) * 512u + (unsigned)row * 4u;
                Ks[sw(a) >> 2] = (&k4.x)[e];
            }
        }
        __syncthreads();
        #pragma unroll
        for (int k = 0; k < 32; k++) {
            unsigned a0 = (unsigned)k * 512u + (unsigned)tx * 32u;
            float4 b0 = *(const float4*)&Ks[sw(a0) >> 2];
            float4 b1 = *(const float4*)&Ks[sw(a0 + 16u) >> 2];
            ull bv0 = pack2(b0.x, b0.y), bv1 = pack2(b0.z, b0.w);
            ull bv2 = pack2(b1.x, b1.y), bv3 = pack2(b1.z, b1.w);
            #pragma unroll
            for (int ii = 0; ii < 8; ii++) {
                float av = Qs[(ty * 8 + ii) * 33 + k];
                ull a2 = pack2(av, av);
                acc[ii][0] = fma2(a2, bv0, acc[ii][0]);
                acc[ii][1] = fma2(a2, bv1, acc[ii][1]);
                acc[ii][2] = fma2(a2, bv2, acc[ii][2]);
                acc[ii][3] = fma2(a2, bv3, acc[ii][3]);
            }
        }
    }

    // ---- epilogue: Ks is dead; alias it as a u16-packed private histogram ----
    unsigned* hist_s = (unsigned*)Ks;     // 2048 u32 = 4096 u16 counters
    __syncthreads();
    for (int i = tid; i < 2048; i += 256) hist_s[i] = 0u;
    __syncthreads();

    int jb = j0 + tx * 8;
    float ikv[8];
    #pragma unroll
    for (int jj = 0; jj < 8; jj++) ikv[jj] = g_invk[bh * SLEN + jb + jj];
    #pragma unroll
    for (int ii = 0; ii < 8; ii++) {
        int row = bh * SLEN + i0 + ty * 8 + ii;
        float iq = g_invq[row];
        float2 c0 = unpack2(acc[ii][0]);
        float2 c1 = unpack2(acc[ii][1]);
        float2 c2 = unpack2(acc[ii][2]);
        float2 c3 = unpack2(acc[ii][3]);
        float v[8];
        v[0] = c0.x * iq * ikv[0]; v[1] = c0.y * iq * ikv[1];
        v[2] = c1.x * iq * ikv[2]; v[3] = c1.y * iq * ikv[3];
        v[4] = c2.x * iq * ikv[4]; v[5] = c2.y * iq * ikv[5];
        v[6] = c3.x * iq * ikv[6]; v[7] = c3.y * iq * ikv[7];
        size_t idx = (size_t)row * SLEN + jb;
        *(float4*)&g_score[idx]     = make_float4(v[0], v[1], v[2], v[3]);
        *(float4*)&g_score[idx + 4] = make_float4(v[4], v[5], v[6], v[7]);
        #pragma unroll
        for (int e = 0; e < 8; e++) {
            unsigned bin = __float_as_uint(fabsf(v[e])) >> 18;   // < 4096 (|v| < 2)
            atomicAdd(&hist_s[bin >> 1], 1u << ((bin & 1u) * 16u));
        }
    }

    __syncthreads();
    for (int i = tid; i < 2048; i += 256) {
        unsigned pr = hist_s[i];
        unsigned lo = pr & 0xFFFFu, hi = pr >> 16;
        if (lo) atomicAdd(&g_hist[2 * i],     lo);
        if (hi) atomicAdd(&g_hist[2 * i + 1], hi);
    }
}

// ---------------- kernel 2.5: scan 4096 bins + edge t table (1 block) -------
__global__ __launch_bounds__(1024) void scan_ttab_kernel() {
    __shared__ unsigned ws[32];
    int tid = threadIdx.x;
    int lane = tid & 31, wid = tid >> 5;
    unsigned c0 = g_hist[tid * 4], c1 = g_hist[tid * 4 + 1];
    unsigned c2 = g_hist[tid * 4 + 2], c3 = g_hist[tid * 4 + 3];
    unsigned tsum = c0 + c1 + c2 + c3;
    unsigned incl = tsum;
    #pragma unroll
    for (int o = 1; o < 32; o <<= 1) {
        unsigned n = __shfl_up_sync(0xffffffffu, incl, o);
        if (lane >= o) incl += n;
    }
    if (lane == 31) ws[wid] = incl;
    __syncthreads();
    if (wid == 0) {
        unsigned v = ws[lane];
        #pragma unroll
        for (int o = 1; o < 32; o <<= 1) {
            unsigned n = __shfl_up_sync(0xffffffffu, v, o);
            if (lane >= o) v += n;
        }
        ws[lane] = v;
    }
    __syncthreads();
    unsigned excl = incl - tsum + (wid ? ws[wid - 1] : 0u);
    const float sA = 1.0f / 33554431.0f;   // 1/(n-1)
    const float sB = 1.0f / 33554432.0f;   // 1/n
    unsigned e0 = excl, e1 = e0 + c0, e2 = e1 + c1, e3 = e2 + c2;
    g_ttab[tid * 4]     = -__logf(fmaf((float)e0, sA, sB));
    g_ttab[tid * 4 + 1] = -__logf(fmaf((float)e1, sA, sB));
    g_ttab[tid * 4 + 2] = -__logf(fmaf((float)e2, sA, sB));
    g_ttab[tid * 4 + 3] = -__logf(fmaf((float)e3, sA, sB));
    if (tid == 1023)
        g_ttab[4096] = -__logf(fmaf((float)(e3 + c3), sA, sB));
}

// ---------------- kernel 3: fused transform + rowsum + out GEMM --------------
// 256 blocks x 128 rows (2 blocks/SM). Transform = smem CDF-table lerp.
__global__ __launch_bounds__(256) void out_kernel(const float* __restrict__ V,
                                                  float* __restrict__ O) {
    __shared__ float Ts[128 * 33];       // t values, i-major odd stride (16.9 KB)
    __shared__ float Vs[32 * 64];        // k-major SW128 (8 KB)
    __shared__ float ttab_s[NBINS + 1];  // 16.4 KB
    __shared__ float spart[256];
    __shared__ float sinv[128];
    int blk = blockIdx.x;                // 0..255
    int bh = blk >> 3;
    int i0 = blk * 128;
    const float* Vb = V + (size_t)bh * SLEN * HD;
    int tid = threadIdx.x;
    int tx = tid & 7, ty = tid >> 3;
    int prow = tid & 127, phalf = tid >> 7;

    for (int i = tid; i < NBINS + 1; i += 256) ttab_s[i] = g_ttab[i];
    __syncthreads();

    ull acc[4][4];
    #pragma unroll
    for (int ii = 0; ii < 4; ii++)
        #pragma unroll
        for (int p = 0; p < 4; p++) acc[ii][p] = 0ull;
    float srow = 0.0f;

    for (int c = 0; c < 32; c++) {   // k chunks of 32
        if (c) __syncthreads();
        // stage V chunk (swizzled): 32 rows x 64 cols
        {
            int kv = tid >> 3;
            int d8 = (tid & 7) * 8;
            const float* vp = &Vb[(c * 32 + kv) * HD + d8];
            #pragma unroll
            for (int h = 0; h < 2; h++) {
                float4 v4 = *(const float4*)&vp[h * 4];
                unsigned a = (unsigned)kv * 256u + (unsigned)(d8 + h * 4) * 4u;
                *(float4*)&Vs[sw(a) >> 2] = v4;
            }
        }
        // stage + transform P: 16 cols of row i0+prow; smem table lerp
        {
            const float* pr = g_score + (size_t)(i0 + prow) * SLEN + c * 32 + phalf * 16;
            float v[16];
            #pragma unroll
            for (int q = 0; q < 4; q++)
                *(float4*)&v[q * 4] = *(const float4*)&pr[q * 4];
            float* trow = &Ts[prow * 33 + phalf * 16];
            #pragma unroll
            for (int e = 0; e < 16; e++) {
                unsigned bits = __float_as_uint(fabsf(v[e]));
                unsigned b = bits >> 18;
                float frac = (float)(bits & 0x3FFFFu) * (1.0f / 262144.0f);
                float t0 = ttab_s[b], t1 = ttab_s[b + 1];
                float t = fmaf(frac, t1 - t0, t0);
                t = (v[e] > 0.0f) ? t : ((v[e] < 0.0f) ? -t : 0.0f);
                srow += fabsf(t);
                trow[e] = t;
            }
        }
        __syncthreads();
        #pragma unroll
        for (int k = 0; k < 32; k++) {
            unsigned a0 = (unsigned)k * 256u + (unsigned)tx * 32u;
            float4 b0 = *(const float4*)&Vs[sw(a0) >> 2];
            float4 b1 = *(const float4*)&Vs[sw(a0 + 16u) >> 2];
            ull bv0 = pack2(b0.x, b0.y), bv1 = pack2(b0.z, b0.w);
            ull bv2 = pack2(b1.x, b1.y), bv3 = pack2(b1.z, b1.w);
            #pragma unroll
            for (int ii = 0; ii < 4; ii++) {
                float av = Ts[(ty * 4 + ii) * 33 + k];
                ull a2 = pack2(av, av);
                acc[ii][0] = fma2(a2, bv0, acc[ii][0]);
                acc[ii][1] = fma2(a2, bv1, acc[ii][1]);
                acc[ii][2] = fma2(a2, bv2, acc[ii][2]);
                acc[ii][3] = fma2(a2, bv3, acc[ii][3]);
            }
        }
    }

    spart[tid] = srow;
    __syncthreads();
    if (tid < 128) sinv[tid] = 1.0f / (spart[tid] + spart[tid + 128]);
    __syncthreads();

    int d0 = tx * 8;
    #pragma unroll
    for (int ii = 0; ii < 4; ii++) {
        int lrow = ty * 4 + ii;
        float s = sinv[lrow];
        float2 c0 = unpack2(acc[ii][0]);
        float2 c1 = unpack2(acc[ii][1]);
        float2 c2 = unpack2(acc[ii][2]);
        float2 c3 = unpack2(acc[ii][3]);
        size_t oidx = (size_t)(i0 + lrow) * HD + d0;
        *(float4*)&O[oidx]     = make_float4(c0.x * s, c0.y * s, c1.x * s, c1.y * s);
        *(float4*)&O[oidx + 4] = make_float4(c2.x * s, c2.y * s, c3.x * s, c3.y * s);
    }
}

// ---------------- launcher ---------------------------------------------------
extern "C" void kernel_launch(void* const* d_in, const int* in_sizes, int n_in,
                              void* d_out, int out_size) {
    const float* Q = (const float*)d_in[0];
    const float* K = (const float*)d_in[1];
    const float* V = (const float*)d_in[2];
    float* O = (float*)d_out;

    zero_hist_kernel<<<NBINS / 256, 256>>>();
    norms_kernel<<<8192, 256>>>(Q, K);
    score_kernel<<<dim3(8, 8, NBH), 256>>>(Q, K);
    scan_ttab_kernel<<<1, 1024>>>();
    out_kernel<<<256, 256>>>(V, O);
}